// round 13
// baseline (speedup 1.0000x reference)
#include <cuda_runtime.h>
#include <cuda_bf16.h>
#include <cstdint>

#define NROWS 131072
#define DDIM  64
#define KC    512
#define BM    256
#define NBLK  (NROWS / BM)
#define NTHR  512
#define MARGIN_TAU 0.015f
#define BIAS 40.0f

// padded smem rows: 72 bf16 elements = 144 bytes (conflict-free ldmatrix)
#define RS 144

// smem byte offsets (all 16B aligned)
#define EH_OFF  0                       // 512 x 144
#define EL_OFF  73728
#define XH_OFF  147456                  // 256 x 144
#define XL_OFF  184320
#define HN_OFF  221184                  // 512 floats: -(0.5||e||^2 + BIAS)
#define IDX_OFF 223232                  // 256 ints
#define CNT_OFF 224256                  // 1 int
#define FL_OFF  224260                  // 256 ints
#define TN_OFF  225536                  // 512 floats (exact R1-chain norms)
#define SMEM_SZ 227584

__device__ __align__(16) unsigned char g_Ebuf[147456];   // eh table + el table
__device__ __align__(16) float g_hn[KC];
__device__ __align__(16) float g_tn[KC];
__device__ float g_loss_acc;
__device__ unsigned int g_done;

__device__ __forceinline__ uint32_t s2u(const void* p) {
    uint32_t a;
    asm("{ .reg .u64 t; cvta.to.shared.u64 t, %1; cvt.u32.u64 %0, t; }" : "=r"(a) : "l"(p));
    return a;
}
__device__ __forceinline__ void cpa16(uint32_t dst, const void* src) {
    asm volatile("cp.async.cg.shared.global [%0], [%1], 16;" :: "r"(dst), "l"(src) : "memory");
}
#define CP_COMMIT() asm volatile("cp.async.commit_group;" ::: "memory")
#define CP_WAIT0()  asm volatile("cp.async.wait_group 0;" ::: "memory")

#define LDSM4(r, addr) \
    asm volatile("ldmatrix.sync.aligned.m8n8.x4.shared.b16 {%0,%1,%2,%3}, [%4];" \
        : "=r"((r)[0]), "=r"((r)[1]), "=r"((r)[2]), "=r"((r)[3]) : "r"(addr))

#define MMA16816(acc, a, b0, b1) \
    asm volatile("mma.sync.aligned.m16n8k16.row.col.f32.bf16.bf16.f32 " \
        "{%0,%1,%2,%3},{%4,%5,%6,%7},{%8,%9},{%0,%1,%2,%3};" \
        : "+f"((acc)[0]), "+f"((acc)[1]), "+f"((acc)[2]), "+f"((acc)[3]) \
        : "r"((a)[0]), "r"((a)[1]), "r"((a)[2]), "r"((a)[3]), "r"(b0), "r"(b1))

__device__ __forceinline__ uint32_t packbf(float lo, float hi) {
    __nv_bfloat162 v = __floats2bfloat162_rn(lo, hi);
    return *(uint32_t*)&v;
}
__device__ __forceinline__ void split1(float v, float& h, float& l) {
    __nv_bfloat16 hb = __float2bfloat16_rn(v);
    h = __bfloat162float(hb);
    l = v - h;                 // exact, so h + l == v exactly
}
__device__ __forceinline__ float bf2f(uint32_t u, int hi) {
    __nv_bfloat162 p = *(__nv_bfloat162*)&u;
    return hi ? __bfloat162float(p.y) : __bfloat162float(p.x);
}
// scores are strictly negative floats: as raw uint bits, umin == float-max.
// Low 9 bits replaced by col: uint ties prefer smaller col == first-max.
__device__ __forceinline__ uint32_t mkkey(float v, int col) {
    return (__float_as_uint(v) & 0xFFFFFE00u) | (uint32_t)col;
}

// ---------- prep: convert E once, biased-neg half-norms, exact norms ----------
__global__ void vq_prep(const float* __restrict__ E) {
    const int k = blockIdx.x * 128 + threadIdx.x;   // grid 4 x 128
    if (k == 0) { g_loss_acc = 0.0f; g_done = 0u; }
    float s = 0.f;
    #pragma unroll 8
    for (int d = 0; d < DDIM; d += 2) {
        float a0 = E[d * KC + k], a1 = E[(d + 1) * KC + k];
        s = fmaf(a0, a0, fmaf(a1, a1, s));
        float h0, l0, h1, l1;
        split1(a0, h0, l0); split1(a1, h1, l1);
        *(uint32_t*)(g_Ebuf + k * RS + d * 2)         = packbf(h0, h1);
        *(uint32_t*)(g_Ebuf + 73728 + k * RS + d * 2) = packbf(l0, l1);
    }
    g_hn[k] = -(0.5f * s + BIAS);       // accumulator init value
    // exact sequential chain matching R1's rescue t[i] (ascending d, single fmaf chain)
    float t = 0.f;
    for (int d = 0; d < DDIM; ++d) {
        float e = E[d * KC + k];
        t = fmaf(e, e, t);
    }
    g_tn[k] = t;
}

extern __shared__ unsigned char smem[];

__global__ __launch_bounds__(NTHR, 1)
void vq_hmma_kernel(const float* __restrict__ x,
                    const float* __restrict__ E,
                    float* __restrict__ out, int loss_pos) {
    const int tid = threadIdx.x;
    const int w   = tid >> 5;            // 0..15
    const int l   = tid & 31;
    const int row0 = blockIdx.x * BM;
    const uint32_t sb = s2u(smem);
    float* hn   = (float*)(smem + HN_OFF);
    float* tns  = (float*)(smem + TN_OFF);
    int*   idxs = (int*)(smem + IDX_OFF);
    int*   fcnt = (int*)(smem + CNT_OFF);
    int*  flagd = (int*)(smem + FL_OFF);
    __shared__ float warpsums[16];

    if (tid == 0) *fcnt = 0;

    // ---- async copy of converted E tables + hn + tn into smem ----
    #pragma unroll
    for (int i = 0; i < 18; ++i) {
        uint32_t off = (uint32_t)(tid + i * NTHR) * 16;
        cpa16(sb + EH_OFF + off, g_Ebuf + off);
    }
    if (tid < 128) {
        cpa16(sb + HN_OFF + tid * 16, (const unsigned char*)g_hn + tid * 16);
        cpa16(sb + TN_OFF + tid * 16, (const unsigned char*)g_tn + tid * 16);
    }
    CP_COMMIT();

    // ---- convert x tile into smem (overlaps with async copies) ----
    {
        const float4* x4 = (const float4*)x + (size_t)row0 * 16;
        #pragma unroll
        for (int i = 0; i < 8; ++i) {
            int idx = tid + i * NTHR;          // 0..4095
            int r = idx >> 4, c4 = idx & 15;
            float4 v = x4[idx];
            float h0,l0,h1,l1,h2,l2,h3,l3;
            split1(v.x, h0, l0); split1(v.y, h1, l1);
            split1(v.z, h2, l2); split1(v.w, h3, l3);
            *(uint2*)(smem + XH_OFF + r * RS + c4 * 8) = make_uint2(packbf(h0, h1), packbf(h2, h3));
            *(uint2*)(smem + XL_OFF + r * RS + c4 * 8) = make_uint2(packbf(l0, l1), packbf(l2, l3));
        }
    }
    CP_WAIT0();
    __syncthreads();

    // ========== main (screening): each warp does 16 rows x 512 codes ==========
    // 2-term approx (xh+xl)·eh = x·eh; acc initialized to -(hn+BIAS) so the
    // MMA output IS score-BIAS, strictly negative. Packed-uint argmax fold.
    uint32_t Ah[4][4], Al[4][4];
    {
        uint32_t abase = (uint32_t)((w * 16 + (l & 15)) * RS + ((l >> 4) << 4));
        #pragma unroll
        for (int ks = 0; ks < 4; ++ks) {
            LDSM4(Ah[ks], sb + XH_OFF + abase + ks * 32);
            LDSM4(Al[ks], sb + XL_OFF + abase + ks * 32);
        }
    }

    uint32_t b1_lo = 0xFFFFFFFFu, b2_lo = 0xFFFFFFFFu;
    uint32_t b1_hi = 0xFFFFFFFFu, b2_hi = 0xFFFFFFFFu;
    const uint32_t brow = (uint32_t)((l & 7) * RS + ((l >> 3) << 4));

    #pragma unroll 1
    for (int g = 0; g < 8; ++g) {
        float acc[8][4];
        #pragma unroll
        for (int t = 0; t < 8; ++t) {
            const int col0 = g * 64 + t * 8 + 2 * (l & 3);
            float2 hv = *(const float2*)(hn + col0);
            acc[t][0] = hv.x; acc[t][1] = hv.y;
            acc[t][2] = hv.x; acc[t][3] = hv.y;
        }

        #pragma unroll
        for (int s = 0; s < 2; ++s) {
            uint32_t beh[8][4];
            #pragma unroll
            for (int t = 0; t < 8; ++t) {
                uint32_t ro = (uint32_t)((g * 64 + t * 8) * RS + s * 64) + brow;
                LDSM4(beh[t], sb + EH_OFF + ro);
            }
            #pragma unroll
            for (int kk = 0; kk < 2; ++kk) {
                const int ks = 2 * s + kk;
                #pragma unroll
                for (int t = 0; t < 8; ++t)
                    MMA16816(acc[t], Ah[ks], beh[t][2 * kk], beh[t][2 * kk + 1]);
                #pragma unroll
                for (int t = 0; t < 8; ++t)
                    MMA16816(acc[t], Al[ks], beh[t][2 * kk], beh[t][2 * kk + 1]);
            }
        }

        // packed-uint fold: LOP3 + 2x IMNMX per value, no predicates, no loads
        #pragma unroll
        for (int t = 0; t < 8; ++t) {
            const int col0 = g * 64 + t * 8 + 2 * (l & 3);
            uint32_t k0, k1;
            k0 = mkkey(acc[t][0], col0);
            k1 = mkkey(acc[t][1], col0 + 1);
            b2_lo = min(b2_lo, max(b1_lo, k0)); b1_lo = min(b1_lo, k0);
            b2_lo = min(b2_lo, max(b1_lo, k1)); b1_lo = min(b1_lo, k1);
            k0 = mkkey(acc[t][2], col0);
            k1 = mkkey(acc[t][3], col0 + 1);
            b2_hi = min(b2_hi, max(b1_hi, k0)); b1_hi = min(b1_hi, k0);
            b2_hi = min(b2_hi, max(b1_hi, k1)); b1_hi = min(b1_hi, k1);
        }
    }

    // reduce across the 4 lanes of each row-quad (integer keys carry indices)
    #pragma unroll
    for (int m = 1; m < 4; m <<= 1) {
        uint32_t o1, o2;
        o1 = __shfl_xor_sync(0xffffffffu, b1_lo, m, 32);
        o2 = __shfl_xor_sync(0xffffffffu, b2_lo, m, 32);
        b2_lo = min(min(b2_lo, o2), max(b1_lo, o1));
        b1_lo = min(b1_lo, o1);
        o1 = __shfl_xor_sync(0xffffffffu, b1_hi, m, 32);
        o2 = __shfl_xor_sync(0xffffffffu, b2_hi, m, 32);
        b2_hi = min(min(b2_hi, o2), max(b1_hi, o1));
        b1_hi = min(b1_hi, o1);
    }
    if ((l & 3) == 0) {
        const int r_lo = w * 16 + (l >> 2);
        const int r_hi = r_lo + 8;
        idxs[r_lo] = (int)(b1_lo & 511u);
        idxs[r_hi] = (int)(b1_hi & 511u);
        float m1 = __uint_as_float(b1_lo & 0xFFFFFE00u);
        float m2 = __uint_as_float(b2_lo & 0xFFFFFE00u);
        if (m1 - m2 < MARGIN_TAU) flagd[atomicAdd(fcnt, 1)] = r_lo;
        m1 = __uint_as_float(b1_hi & 0xFFFFFE00u);
        m2 = __uint_as_float(b2_hi & 0xFFFFFE00u);
        if (m1 - m2 < MARGIN_TAU) flagd[atomicAdd(fcnt, 1)] = r_hi;
    }
    __syncthreads();

    // ===== rescue: bit-exact replica of the R1 scalar scoring for flagged rows =====
    {
        const int cnt = *fcnt;
        for (int j = w; j < cnt; j += 16) {
            const int r = flagd[j];
            const float* xr = x + (size_t)(row0 + r) * DDIM;
            float s[16];
            #pragma unroll
            for (int i = 0; i < 16; ++i) s[i] = 0.f;
            #pragma unroll 4
            for (int d = 0; d < DDIM; ++d) {
                const float xd = xr[d];
                const float* Ed = E + d * KC + l;
                #pragma unroll
                for (int i = 0; i < 16; ++i)
                    s[i] = fmaf(xd, Ed[i * 32], s[i]);
            }
            float best = -3.4e38f; int bi = 0;
            #pragma unroll
            for (int i = 0; i < 16; ++i) {
                int k = i * 32 + l;
                float sc = s[i] - 0.5f * tns[k];
                if (sc > best) { best = sc; bi = k; }
            }
            #pragma unroll
            for (int m = 1; m < 32; m <<= 1) {
                float so = __shfl_xor_sync(0xffffffffu, best, m, 32);
                int   io = __shfl_xor_sync(0xffffffffu, bi,   m, 32);
                if (so > best || (so == best && io < bi)) { best = so; bi = io; }
            }
            if (l == 0) idxs[r] = bi;
        }
    }
    __syncthreads();

    // ======= epilogue (all-smem, exact reconstruction): 2 threads per row =======
    float lp = 0.0f;
    {
        const int r = tid >> 1, half = tid & 1;
        const int k = idxs[r];
        const unsigned char* ehp = smem + EH_OFF + k * RS + half * 64;
        const unsigned char* elp = smem + EL_OFF + k * RS + half * 64;
        const unsigned char* xhp = smem + XH_OFF + r * RS + half * 64;
        const unsigned char* xlp = smem + XL_OFF + r * RS + half * 64;
        float4* og = (float4*)(out + (size_t)(row0 + r) * DDIM + half * 32);
        #pragma unroll
        for (int j = 0; j < 8; ++j) {
            uint32_t he  = *(const uint32_t*)(ehp + j * 8);
            uint32_t he2 = *(const uint32_t*)(ehp + j * 8 + 4);
            uint32_t le  = *(const uint32_t*)(elp + j * 8);
            uint32_t le2 = *(const uint32_t*)(elp + j * 8 + 4);
            uint32_t hx  = *(const uint32_t*)(xhp + j * 8);
            uint32_t hx2 = *(const uint32_t*)(xhp + j * 8 + 4);
            uint32_t lx  = *(const uint32_t*)(xlp + j * 8);
            uint32_t lx2 = *(const uint32_t*)(xlp + j * 8 + 4);
            float q0 = bf2f(he, 0) + bf2f(le, 0);
            float q1 = bf2f(he, 1) + bf2f(le, 1);
            float q2 = bf2f(he2, 0) + bf2f(le2, 0);
            float q3 = bf2f(he2, 1) + bf2f(le2, 1);
            float x0 = bf2f(hx, 0) + bf2f(lx, 0);
            float x1 = bf2f(hx, 1) + bf2f(lx, 1);
            float x2 = bf2f(hx2, 0) + bf2f(lx2, 0);
            float x3 = bf2f(hx2, 1) + bf2f(lx2, 1);
            float d0 = q0 - x0, d1 = q1 - x1, d2 = q2 - x2, d3 = q3 - x3;
            lp = fmaf(d0, d0, lp); lp = fmaf(d1, d1, lp);
            lp = fmaf(d2, d2, lp); lp = fmaf(d3, d3, lp);
            og[j] = make_float4(x0 + d0, x1 + d1, x2 + d2, x3 + d3);
        }
    }
    #pragma unroll
    for (int m = 16; m > 0; m >>= 1)
        lp += __shfl_xor_sync(0xffffffffu, lp, m, 32);
    if (l == 0) warpsums[w] = lp;
    __syncthreads();

    // single loss atomic per CTA; last CTA writes the final loss
    if (tid == 0) {
        float s = 0.f;
        #pragma unroll
        for (int i = 0; i < 16; ++i) s += warpsums[i];
        atomicAdd(&g_loss_acc, s);
        __threadfence();
        unsigned int o = atomicAdd(&g_done, 1u);
        if (o == (unsigned)(NBLK - 1)) {
            float tot = atomicAdd(&g_loss_acc, 0.0f);
            out[loss_pos] = 2.0f * tot / 8388608.0f;
        }
    }
}

extern "C" void kernel_launch(void* const* d_in, const int* in_sizes, int n_in,
                              void* d_out, int out_size) {
    const float* x = (const float*)d_in[0];   // [32,4096,64] fp32
    const float* E = (const float*)d_in[1];   // [64,512] fp32
    float* out = (float*)d_out;

    cudaFuncSetAttribute(vq_hmma_kernel,
                         cudaFuncAttributeMaxDynamicSharedMemorySize, SMEM_SZ);

    vq_prep<<<4, 128>>>(E);
    vq_hmma_kernel<<<NBLK, NTHR, SMEM_SZ>>>(x, E, out, out_size - 1);
}

// round 14
// speedup vs baseline: 1.0810x; 1.0810x over previous
#include <cuda_runtime.h>
#include <cuda_bf16.h>
#include <cstdint>

#define NROWS 131072
#define DDIM  64
#define KC    512
#define BM    256
#define NBLK  (NROWS / BM)
#define NTHR  512
#define MARGIN_TAU 0.01f

// padded smem rows: 72 bf16 elements = 144 bytes (conflict-free ldmatrix)
#define RS 144

// smem byte offsets (all 16B aligned)
#define EH_OFF  0                       // 512 x 144
#define EL_OFF  73728
#define XH_OFF  147456                  // 256 x 144
#define XL_OFF  184320
#define HN_OFF  221184                  // 512 floats (0.5||e||^2)
#define IDX_OFF 223232                  // 256 ints
#define CNT_OFF 224256                  // 1 int
#define FL_OFF  224260                  // 256 ints
#define TN_OFF  225536                  // 512 floats (exact R1-chain norms)
#define SMEM_SZ 227584

__device__ __align__(16) unsigned char g_Ebuf[147456];   // eh table + el table
__device__ __align__(16) float g_hn[KC];
__device__ __align__(16) float g_tn[KC];
__device__ float g_loss_acc;
__device__ unsigned int g_done;

__device__ __forceinline__ uint32_t s2u(const void* p) {
    uint32_t a;
    asm("{ .reg .u64 t; cvta.to.shared.u64 t, %1; cvt.u32.u64 %0, t; }" : "=r"(a) : "l"(p));
    return a;
}
__device__ __forceinline__ void cpa16(uint32_t dst, const void* src) {
    asm volatile("cp.async.cg.shared.global [%0], [%1], 16;" :: "r"(dst), "l"(src) : "memory");
}
#define CP_COMMIT() asm volatile("cp.async.commit_group;" ::: "memory")
#define CP_WAIT0()  asm volatile("cp.async.wait_group 0;" ::: "memory")

#define LDSM4(r, addr) \
    asm volatile("ldmatrix.sync.aligned.m8n8.x4.shared.b16 {%0,%1,%2,%3}, [%4];" \
        : "=r"((r)[0]), "=r"((r)[1]), "=r"((r)[2]), "=r"((r)[3]) : "r"(addr))

#define MMA16816(acc, a, b0, b1) \
    asm volatile("mma.sync.aligned.m16n8k16.row.col.f32.bf16.bf16.f32 " \
        "{%0,%1,%2,%3},{%4,%5,%6,%7},{%8,%9},{%0,%1,%2,%3};" \
        : "+f"((acc)[0]), "+f"((acc)[1]), "+f"((acc)[2]), "+f"((acc)[3]) \
        : "r"((a)[0]), "r"((a)[1]), "r"((a)[2]), "r"((a)[3]), "r"(b0), "r"(b1))

__device__ __forceinline__ uint32_t packbf(float lo, float hi) {
    __nv_bfloat162 v = __floats2bfloat162_rn(lo, hi);
    return *(uint32_t*)&v;
}
__device__ __forceinline__ void split1(float v, float& h, float& l) {
    __nv_bfloat16 hb = __float2bfloat16_rn(v);
    h = __bfloat162float(hb);
    l = v - h;                 // exact, so h + l == v exactly
}
__device__ __forceinline__ float bf2f(uint32_t u, int hi) {
    __nv_bfloat162 p = *(__nv_bfloat162*)&u;
    return hi ? __bfloat162float(p.y) : __bfloat162float(p.x);
}

// ---------- prep: convert E once, half-norms, exact norms ----------
__global__ void vq_prep(const float* __restrict__ E) {
    const int k = blockIdx.x * 128 + threadIdx.x;   // grid 4 x 128
    if (k == 0) { g_loss_acc = 0.0f; g_done = 0u; }
    float s = 0.f;
    #pragma unroll 8
    for (int d = 0; d < DDIM; d += 2) {
        float a0 = E[d * KC + k], a1 = E[(d + 1) * KC + k];
        s = fmaf(a0, a0, fmaf(a1, a1, s));
        float h0, l0, h1, l1;
        split1(a0, h0, l0); split1(a1, h1, l1);
        *(uint32_t*)(g_Ebuf + k * RS + d * 2)         = packbf(h0, h1);
        *(uint32_t*)(g_Ebuf + 73728 + k * RS + d * 2) = packbf(l0, l1);
    }
    g_hn[k] = 0.5f * s;
    // exact sequential chain matching R1's rescue t[i]
    float t = 0.f;
    for (int d = 0; d < DDIM; ++d) {
        float e = E[d * KC + k];
        t = fmaf(e, e, t);
    }
    g_tn[k] = t;
}

// ---- mainloop building blocks (macros => static register addressing) ----
#define ZERO_ACC(ACC) \
    _Pragma("unroll") \
    for (int t = 0; t < 4; ++t) { \
        ACC[t][0] = 0.f; ACC[t][1] = 0.f; ACC[t][2] = 0.f; ACC[t][3] = 0.f; \
    }

#define LOAD_BEH(c, s) \
    _Pragma("unroll") \
    for (int t = 0; t < 4; ++t) { \
        uint32_t ro = (uint32_t)(((c) * 32 + t * 8) * RS + (s) * 64) + brow; \
        LDSM4(beh[t], sb + EH_OFF + ro); \
    }

#define MMA_SEG(ACC, s) \
    _Pragma("unroll") \
    for (int kk = 0; kk < 2; ++kk) { \
        _Pragma("unroll") \
        for (int t = 0; t < 4; ++t) \
            MMA16816(ACC[t], Ah[2 * (s) + kk], beh[t][2 * kk], beh[t][2 * kk + 1]); \
        _Pragma("unroll") \
        for (int t = 0; t < 4; ++t) \
            MMA16816(ACC[t], Al[2 * (s) + kk], beh[t][2 * kk], beh[t][2 * kk + 1]); \
    }

#define FOLD(ACC, fc) \
    _Pragma("unroll") \
    for (int t = 0; t < 4; ++t) { \
        const int col0 = (fc) * 32 + t * 8 + 2 * (l & 3); \
        float2 h2 = *(const float2*)(hn + col0); \
        float sc; \
        sc = ACC[t][0] - h2.x; \
        b2_lo = fmaxf(b2_lo, fminf(b1_lo, sc)); \
        bi_lo = (sc > b1_lo) ? col0 : bi_lo; \
        b1_lo = fmaxf(b1_lo, sc); \
        sc = ACC[t][1] - h2.y; \
        b2_lo = fmaxf(b2_lo, fminf(b1_lo, sc)); \
        bi_lo = (sc > b1_lo) ? (col0 + 1) : bi_lo; \
        b1_lo = fmaxf(b1_lo, sc); \
        sc = ACC[t][2] - h2.x; \
        b2_hi = fmaxf(b2_hi, fminf(b1_hi, sc)); \
        bi_hi = (sc > b1_hi) ? col0 : bi_hi; \
        b1_hi = fmaxf(b1_hi, sc); \
        sc = ACC[t][3] - h2.y; \
        b2_hi = fmaxf(b2_hi, fminf(b1_hi, sc)); \
        bi_hi = (sc > b1_hi) ? (col0 + 1) : bi_hi; \
        b1_hi = fmaxf(b1_hi, sc); \
    }

// one pipeline step: compute chunk c into ACC while folding FACC (chunk fc)
#define STEP(c, ACC, FACC, fc) \
    ZERO_ACC(ACC); \
    LOAD_BEH(c, 0); \
    MMA_SEG(ACC, 0); \
    LOAD_BEH(c, 1); \
    FOLD(FACC, fc); \
    MMA_SEG(ACC, 1);

extern __shared__ unsigned char smem[];

__global__ __launch_bounds__(NTHR, 1)
void vq_hmma_kernel(const float* __restrict__ x,
                    const float* __restrict__ E,
                    float* __restrict__ out, int loss_pos) {
    const int tid = threadIdx.x;
    const int w   = tid >> 5;            // 0..15
    const int l   = tid & 31;
    const int row0 = blockIdx.x * BM;
    const uint32_t sb = s2u(smem);
    float* hn   = (float*)(smem + HN_OFF);
    float* tns  = (float*)(smem + TN_OFF);
    int*   idxs = (int*)(smem + IDX_OFF);
    int*   fcnt = (int*)(smem + CNT_OFF);
    int*  flagd = (int*)(smem + FL_OFF);
    __shared__ float warpsums[16];

    if (tid == 0) *fcnt = 0;

    // ---- async copy of converted E tables + hn + tn into smem ----
    #pragma unroll
    for (int i = 0; i < 18; ++i) {
        uint32_t off = (uint32_t)(tid + i * NTHR) * 16;
        cpa16(sb + EH_OFF + off, g_Ebuf + off);
    }
    if (tid < 128) {
        cpa16(sb + HN_OFF + tid * 16, (const unsigned char*)g_hn + tid * 16);
        cpa16(sb + TN_OFF + tid * 16, (const unsigned char*)g_tn + tid * 16);
    }
    CP_COMMIT();

    // ---- convert x tile into smem (overlaps with async copies) ----
    {
        const float4* x4 = (const float4*)x + (size_t)row0 * 16;
        #pragma unroll
        for (int i = 0; i < 8; ++i) {
            int idx = tid + i * NTHR;          // 0..4095
            int r = idx >> 4, c4 = idx & 15;
            float4 v = x4[idx];
            float h0,l0,h1,l1,h2,l2,h3,l3;
            split1(v.x, h0, l0); split1(v.y, h1, l1);
            split1(v.z, h2, l2); split1(v.w, h3, l3);
            *(uint2*)(smem + XH_OFF + r * RS + c4 * 8) = make_uint2(packbf(h0, h1), packbf(h2, h3));
            *(uint2*)(smem + XL_OFF + r * RS + c4 * 8) = make_uint2(packbf(l0, l1), packbf(l2, l3));
        }
    }
    CP_WAIT0();
    __syncthreads();

    // ========== main (screening): each warp does 16 rows x 512 codes ==========
    // 2-term approx (xh+xl)·eh = x·eh, error ~1.1e-3 std, gated by tau=0.01.
    // 16 chunks x 32 codes, software-pipelined: fold of chunk c-1 sits inside
    // chunk c's stream, so no fold wall between MMA bursts.
    uint32_t Ah[4][4], Al[4][4];
    {
        uint32_t abase = (uint32_t)((w * 16 + (l & 15)) * RS + ((l >> 4) << 4));
        #pragma unroll
        for (int ks = 0; ks < 4; ++ks) {
            LDSM4(Ah[ks], sb + XH_OFF + abase + ks * 32);
            LDSM4(Al[ks], sb + XL_OFF + abase + ks * 32);
        }
    }

    float b1_lo = -3.4e38f, b1_hi = -3.4e38f;
    float b2_lo = -3.4e38f, b2_hi = -3.4e38f;
    int   bi_lo = 0, bi_hi = 0;
    const uint32_t brow = (uint32_t)((l & 7) * RS + ((l >> 3) << 4));

    {
        uint32_t beh[4][4];
        float accA[4][4], accB[4][4];

        // prologue: chunk 0 -> accA (no fold yet)
        ZERO_ACC(accA);
        LOAD_BEH(0, 0);
        MMA_SEG(accA, 0);
        LOAD_BEH(0, 1);
        MMA_SEG(accA, 1);

        // steady state: 2 chunks per iteration, ping-pong accumulators
        #pragma unroll 1
        for (int cc = 1; cc < 15; cc += 2) {
            STEP(cc,     accB, accA, cc - 1);
            STEP(cc + 1, accA, accB, cc);
        }
        // cc = 15
        STEP(15, accB, accA, 14);
        FOLD(accB, 15);
    }

    // reduce across the 4 lanes of each row-quad, carrying second-best
    #pragma unroll
    for (int m = 1; m < 4; m <<= 1) {
        float so, s2o; int io;
        so  = __shfl_xor_sync(0xffffffffu, b1_lo, m, 32);
        s2o = __shfl_xor_sync(0xffffffffu, b2_lo, m, 32);
        io  = __shfl_xor_sync(0xffffffffu, bi_lo, m, 32);
        b2_lo = fmaxf(fminf(b1_lo, so), fmaxf(b2_lo, s2o));
        if (so > b1_lo || (so == b1_lo && io < bi_lo)) { b1_lo = so; bi_lo = io; }
        so  = __shfl_xor_sync(0xffffffffu, b1_hi, m, 32);
        s2o = __shfl_xor_sync(0xffffffffu, b2_hi, m, 32);
        io  = __shfl_xor_sync(0xffffffffu, bi_hi, m, 32);
        b2_hi = fmaxf(fminf(b1_hi, so), fmaxf(b2_hi, s2o));
        if (so > b1_hi || (so == b1_hi && io < bi_hi)) { b1_hi = so; bi_hi = io; }
    }
    if ((l & 3) == 0) {
        const int r_lo = w * 16 + (l >> 2);
        const int r_hi = r_lo + 8;
        idxs[r_lo] = bi_lo;
        idxs[r_hi] = bi_hi;
        if (b1_lo - b2_lo < MARGIN_TAU) flagd[atomicAdd(fcnt, 1)] = r_lo;
        if (b1_hi - b2_hi < MARGIN_TAU) flagd[atomicAdd(fcnt, 1)] = r_hi;
    }
    __syncthreads();

    // ===== rescue: bit-exact replica of the R1 scalar scoring for flagged rows =====
    {
        const int cnt = *fcnt;
        for (int j = w; j < cnt; j += 16) {
            const int r = flagd[j];
            const float* xr = x + (size_t)(row0 + r) * DDIM;
            float s[16];
            #pragma unroll
            for (int i = 0; i < 16; ++i) s[i] = 0.f;
            #pragma unroll 4
            for (int d = 0; d < DDIM; ++d) {
                const float xd = xr[d];
                const float* Ed = E + d * KC + l;
                #pragma unroll
                for (int i = 0; i < 16; ++i)
                    s[i] = fmaf(xd, Ed[i * 32], s[i]);
            }
            float best = -3.4e38f; int bi = 0;
            #pragma unroll
            for (int i = 0; i < 16; ++i) {
                int k = i * 32 + l;
                float sc = s[i] - 0.5f * tns[k];
                if (sc > best) { best = sc; bi = k; }
            }
            #pragma unroll
            for (int m = 1; m < 32; m <<= 1) {
                float so = __shfl_xor_sync(0xffffffffu, best, m, 32);
                int   io = __shfl_xor_sync(0xffffffffu, bi,   m, 32);
                if (so > best || (so == best && io < bi)) { best = so; bi = io; }
            }
            if (l == 0) idxs[r] = bi;
        }
    }
    __syncthreads();

    // ======= epilogue (all-smem, exact reconstruction): 2 threads per row =======
    float lp = 0.0f;
    {
        const int r = tid >> 1, half = tid & 1;
        const int k = idxs[r];
        const unsigned char* ehp = smem + EH_OFF + k * RS + half * 64;
        const unsigned char* elp = smem + EL_OFF + k * RS + half * 64;
        const unsigned char* xhp = smem + XH_OFF + r * RS + half * 64;
        const unsigned char* xlp = smem + XL_OFF + r * RS + half * 64;
        float4* og = (float4*)(out + (size_t)(row0 + r) * DDIM + half * 32);
        #pragma unroll
        for (int j = 0; j < 8; ++j) {
            uint32_t he  = *(const uint32_t*)(ehp + j * 8);
            uint32_t he2 = *(const uint32_t*)(ehp + j * 8 + 4);
            uint32_t le  = *(const uint32_t*)(elp + j * 8);
            uint32_t le2 = *(const uint32_t*)(elp + j * 8 + 4);
            uint32_t hx  = *(const uint32_t*)(xhp + j * 8);
            uint32_t hx2 = *(const uint32_t*)(xhp + j * 8 + 4);
            uint32_t lx  = *(const uint32_t*)(xlp + j * 8);
            uint32_t lx2 = *(const uint32_t*)(xlp + j * 8 + 4);
            float q0 = bf2f(he, 0) + bf2f(le, 0);
            float q1 = bf2f(he, 1) + bf2f(le, 1);
            float q2 = bf2f(he2, 0) + bf2f(le2, 0);
            float q3 = bf2f(he2, 1) + bf2f(le2, 1);
            float x0 = bf2f(hx, 0) + bf2f(lx, 0);
            float x1 = bf2f(hx, 1) + bf2f(lx, 1);
            float x2 = bf2f(hx2, 0) + bf2f(lx2, 0);
            float x3 = bf2f(hx2, 1) + bf2f(lx2, 1);
            float d0 = q0 - x0, d1 = q1 - x1, d2 = q2 - x2, d3 = q3 - x3;
            lp = fmaf(d0, d0, lp); lp = fmaf(d1, d1, lp);
            lp = fmaf(d2, d2, lp); lp = fmaf(d3, d3, lp);
            og[j] = make_float4(x0 + d0, x1 + d1, x2 + d2, x3 + d3);
        }
    }
    #pragma unroll
    for (int m = 16; m > 0; m >>= 1)
        lp += __shfl_xor_sync(0xffffffffu, lp, m, 32);
    if (l == 0) warpsums[w] = lp;
    __syncthreads();

    // single loss atomic per CTA; last CTA writes the final loss
    if (tid == 0) {
        float s = 0.f;
        #pragma unroll
        for (int i = 0; i < 16; ++i) s += warpsums[i];
        atomicAdd(&g_loss_acc, s);
        __threadfence();
        unsigned int o = atomicAdd(&g_done, 1u);
        if (o == (unsigned)(NBLK - 1)) {
            float tot = atomicAdd(&g_loss_acc, 0.0f);
            out[loss_pos] = 2.0f * tot / 8388608.0f;
        }
    }
}

extern "C" void kernel_launch(void* const* d_in, const int* in_sizes, int n_in,
                              void* d_out, int out_size) {
    const float* x = (const float*)d_in[0];   // [32,4096,64] fp32
    const float* E = (const float*)d_in[1];   // [64,512] fp32
    float* out = (float*)d_out;

    cudaFuncSetAttribute(vq_hmma_kernel,
                         cudaFuncAttributeMaxDynamicSharedMemorySize, SMEM_SZ);

    vq_prep<<<4, 128>>>(E);
    vq_hmma_kernel<<<NBLK, NTHR, SMEM_SZ>>>(x, E, out, out_size - 1);
}

// round 15
// speedup vs baseline: 1.3478x; 1.2468x over previous
#include <cuda_runtime.h>
#include <cuda_fp16.h>
#include <cstdint>

#define NROWS 131072
#define DDIM  64
#define KC    512
#define BM    256
#define NBLK  (NROWS / BM)
#define NTHR  512
#define MARGIN_TAU 0.006f

// padded smem rows: 72 fp16 elements = 144 bytes (conflict-free ldmatrix)
#define RS 144

// smem byte offsets (all 16B aligned)
#define EH_OFF  0                       // 512 x 144 (fp16 high parts)
#define EL_OFF  73728                   // 512 x 144 (fp16 low parts)
#define XH_OFF  147456                  // 256 x 144
#define XL_OFF  184320
#define HN_OFF  221184                  // 512 floats (0.5||e||^2)
#define IDX_OFF 223232                  // 256 ints
#define CNT_OFF 224256                  // 1 int
#define FL_OFF  224260                  // 256 ints
#define TN_OFF  225536                  // 512 floats (exact R1-chain norms)
#define SMEM_SZ 227584

__device__ __align__(16) unsigned char g_Ebuf[147456];   // h16 table + l16 table
__device__ __align__(16) float g_hn[KC];
__device__ __align__(16) float g_tn[KC];
__device__ float g_loss_acc;
__device__ unsigned int g_done;

__device__ __forceinline__ uint32_t s2u(const void* p) {
    uint32_t a;
    asm("{ .reg .u64 t; cvta.to.shared.u64 t, %1; cvt.u32.u64 %0, t; }" : "=r"(a) : "l"(p));
    return a;
}
__device__ __forceinline__ void cpa16(uint32_t dst, const void* src) {
    asm volatile("cp.async.cg.shared.global [%0], [%1], 16;" :: "r"(dst), "l"(src) : "memory");
}
#define CP_COMMIT() asm volatile("cp.async.commit_group;" ::: "memory")
#define CP_WAIT0()  asm volatile("cp.async.wait_group 0;" ::: "memory")

#define LDSM4(r, addr) \
    asm volatile("ldmatrix.sync.aligned.m8n8.x4.shared.b16 {%0,%1,%2,%3}, [%4];" \
        : "=r"((r)[0]), "=r"((r)[1]), "=r"((r)[2]), "=r"((r)[3]) : "r"(addr))

#define MMAH16(acc, a, b0, b1) \
    asm volatile("mma.sync.aligned.m16n8k16.row.col.f32.f16.f16.f32 " \
        "{%0,%1,%2,%3},{%4,%5,%6,%7},{%8,%9},{%0,%1,%2,%3};" \
        : "+f"((acc)[0]), "+f"((acc)[1]), "+f"((acc)[2]), "+f"((acc)[3]) \
        : "r"((a)[0]), "r"((a)[1]), "r"((a)[2]), "r"((a)[3]), "r"(b0), "r"(b1))

__device__ __forceinline__ uint32_t packh(float lo, float hi) {
    __half2 v = __floats2half2_rn(lo, hi);
    return *(uint32_t*)&v;
}
// fp16 split: h = rn16(v), l = rn16(v - h). h+l == v to ~2^-23 relative.
__device__ __forceinline__ void split1(float v, float& h, float& l) {
    __half hb = __float2half_rn(v);
    h = __half2float(hb);
    l = v - h;
}
__device__ __forceinline__ float hf2f(uint32_t u, int hi) {
    __half2 p = *(__half2*)&u;
    return hi ? __half2float(p.y) : __half2float(p.x);
}

// ---------- prep: convert E once, half-norms, exact norms ----------
__global__ void vq_prep(const float* __restrict__ E) {
    const int k = blockIdx.x * 128 + threadIdx.x;   // grid 4 x 128
    if (k == 0) { g_loss_acc = 0.0f; g_done = 0u; }
    float s = 0.f;
    #pragma unroll 8
    for (int d = 0; d < DDIM; d += 2) {
        float a0 = E[d * KC + k], a1 = E[(d + 1) * KC + k];
        s = fmaf(a0, a0, fmaf(a1, a1, s));
        float h0, l0, h1, l1;
        split1(a0, h0, l0); split1(a1, h1, l1);
        *(uint32_t*)(g_Ebuf + k * RS + d * 2)         = packh(h0, h1);
        *(uint32_t*)(g_Ebuf + 73728 + k * RS + d * 2) = packh(l0, l1);
    }
    g_hn[k] = 0.5f * s;
    // exact sequential chain matching R1's rescue t[i]
    float t = 0.f;
    for (int d = 0; d < DDIM; ++d) {
        float e = E[d * KC + k];
        t = fmaf(e, e, t);
    }
    g_tn[k] = t;
}

extern __shared__ unsigned char smem[];

__global__ __launch_bounds__(NTHR, 1)
void vq_hmma_kernel(const float* __restrict__ x,
                    const float* __restrict__ E,
                    float* __restrict__ out, int loss_pos) {
    const int tid = threadIdx.x;
    const int w   = tid >> 5;            // 0..15
    const int l   = tid & 31;
    const int row0 = blockIdx.x * BM;
    const uint32_t sb = s2u(smem);
    float* hn   = (float*)(smem + HN_OFF);
    float* tns  = (float*)(smem + TN_OFF);
    int*   idxs = (int*)(smem + IDX_OFF);
    int*   fcnt = (int*)(smem + CNT_OFF);
    int*  flagd = (int*)(smem + FL_OFF);
    __shared__ float warpsums[16];

    if (tid == 0) *fcnt = 0;

    // ---- async copy of converted E tables + hn + tn into smem ----
    #pragma unroll
    for (int i = 0; i < 18; ++i) {
        uint32_t off = (uint32_t)(tid + i * NTHR) * 16;
        cpa16(sb + EH_OFF + off, g_Ebuf + off);
    }
    if (tid < 128) {
        cpa16(sb + HN_OFF + tid * 16, (const unsigned char*)g_hn + tid * 16);
        cpa16(sb + TN_OFF + tid * 16, (const unsigned char*)g_tn + tid * 16);
    }
    CP_COMMIT();

    // ---- convert x tile into smem (overlaps with async copies) ----
    {
        const float4* x4 = (const float4*)x + (size_t)row0 * 16;
        #pragma unroll
        for (int i = 0; i < 8; ++i) {
            int idx = tid + i * NTHR;          // 0..4095
            int r = idx >> 4, c4 = idx & 15;
            float4 v = x4[idx];
            float h0,l0,h1,l1,h2,l2,h3,l3;
            split1(v.x, h0, l0); split1(v.y, h1, l1);
            split1(v.z, h2, l2); split1(v.w, h3, l3);
            *(uint2*)(smem + XH_OFF + r * RS + c4 * 8) = make_uint2(packh(h0, h1), packh(h2, h3));
            *(uint2*)(smem + XL_OFF + r * RS + c4 * 8) = make_uint2(packh(l0, l1), packh(l2, l3));
        }
    }
    CP_WAIT0();
    __syncthreads();

    // ========== main (screening): each warp does 16 rows x 512 codes ==========
    // Single-term fp16 approx xh16·eh16; error ~3e-4 std (11-bit mantissa),
    // gated by MARGIN_TAU = 0.006 (>=15 sigma). 8 groups x 64 codes, 8 acc chains.
    uint32_t Ah[4][4];
    {
        uint32_t abase = (uint32_t)((w * 16 + (l & 15)) * RS + ((l >> 4) << 4));
        #pragma unroll
        for (int ks = 0; ks < 4; ++ks)
            LDSM4(Ah[ks], sb + XH_OFF + abase + ks * 32);
    }

    float b1_lo = -3.4e38f, b1_hi = -3.4e38f;
    float b2_lo = -3.4e38f, b2_hi = -3.4e38f;
    int   bi_lo = 0, bi_hi = 0;
    const uint32_t brow = (uint32_t)((l & 7) * RS + ((l >> 3) << 4));

    #pragma unroll 1
    for (int g = 0; g < 8; ++g) {
        float acc[8][4];
        #pragma unroll
        for (int t = 0; t < 8; ++t)
            #pragma unroll
            for (int j = 0; j < 4; ++j) acc[t][j] = 0.f;

        #pragma unroll
        for (int s = 0; s < 2; ++s) {
            uint32_t beh[8][4];
            #pragma unroll
            for (int t = 0; t < 8; ++t) {
                uint32_t ro = (uint32_t)((g * 64 + t * 8) * RS + s * 64) + brow;
                LDSM4(beh[t], sb + EH_OFF + ro);
            }
            #pragma unroll
            for (int kk = 0; kk < 2; ++kk) {
                const int ks = 2 * s + kk;
                #pragma unroll
                for (int t = 0; t < 8; ++t)
                    MMAH16(acc[t], Ah[ks], beh[t][2 * kk], beh[t][2 * kk + 1]);
            }
        }

        // branchless fold: FMNMX/SEL chains, ascending cols = first-max
        #pragma unroll
        for (int t = 0; t < 8; ++t) {
            const int col0 = g * 64 + t * 8 + 2 * (l & 3);
            float2 h2 = *(const float2*)(hn + col0);
            float sc;
            sc = acc[t][0] - h2.x;
            b2_lo = fmaxf(b2_lo, fminf(b1_lo, sc));
            bi_lo = (sc > b1_lo) ? col0 : bi_lo;
            b1_lo = fmaxf(b1_lo, sc);
            sc = acc[t][1] - h2.y;
            b2_lo = fmaxf(b2_lo, fminf(b1_lo, sc));
            bi_lo = (sc > b1_lo) ? (col0 + 1) : bi_lo;
            b1_lo = fmaxf(b1_lo, sc);
            sc = acc[t][2] - h2.x;
            b2_hi = fmaxf(b2_hi, fminf(b1_hi, sc));
            bi_hi = (sc > b1_hi) ? col0 : bi_hi;
            b1_hi = fmaxf(b1_hi, sc);
            sc = acc[t][3] - h2.y;
            b2_hi = fmaxf(b2_hi, fminf(b1_hi, sc));
            bi_hi = (sc > b1_hi) ? (col0 + 1) : bi_hi;
            b1_hi = fmaxf(b1_hi, sc);
        }
    }

    // reduce across the 4 lanes of each row-quad, carrying second-best
    #pragma unroll
    for (int m = 1; m < 4; m <<= 1) {
        float so, s2o; int io;
        so  = __shfl_xor_sync(0xffffffffu, b1_lo, m, 32);
        s2o = __shfl_xor_sync(0xffffffffu, b2_lo, m, 32);
        io  = __shfl_xor_sync(0xffffffffu, bi_lo, m, 32);
        b2_lo = fmaxf(fminf(b1_lo, so), fmaxf(b2_lo, s2o));
        if (so > b1_lo || (so == b1_lo && io < bi_lo)) { b1_lo = so; bi_lo = io; }
        so  = __shfl_xor_sync(0xffffffffu, b1_hi, m, 32);
        s2o = __shfl_xor_sync(0xffffffffu, b2_hi, m, 32);
        io  = __shfl_xor_sync(0xffffffffu, bi_hi, m, 32);
        b2_hi = fmaxf(fminf(b1_hi, so), fmaxf(b2_hi, s2o));
        if (so > b1_hi || (so == b1_hi && io < bi_hi)) { b1_hi = so; bi_hi = io; }
    }
    if ((l & 3) == 0) {
        const int r_lo = w * 16 + (l >> 2);
        const int r_hi = r_lo + 8;
        idxs[r_lo] = bi_lo;
        idxs[r_hi] = bi_hi;
        if (b1_lo - b2_lo < MARGIN_TAU) flagd[atomicAdd(fcnt, 1)] = r_lo;
        if (b1_hi - b2_hi < MARGIN_TAU) flagd[atomicAdd(fcnt, 1)] = r_hi;
    }
    __syncthreads();

    // ===== rescue: bit-exact replica of the R1 scalar scoring for flagged rows =====
    {
        const int cnt = *fcnt;
        for (int j = w; j < cnt; j += 16) {
            const int r = flagd[j];
            const float* xr = x + (size_t)(row0 + r) * DDIM;
            float s[16];
            #pragma unroll
            for (int i = 0; i < 16; ++i) s[i] = 0.f;
            #pragma unroll 4
            for (int d = 0; d < DDIM; ++d) {
                const float xd = xr[d];
                const float* Ed = E + d * KC + l;
                #pragma unroll
                for (int i = 0; i < 16; ++i)
                    s[i] = fmaf(xd, Ed[i * 32], s[i]);
            }
            float best = -3.4e38f; int bi = 0;
            #pragma unroll
            for (int i = 0; i < 16; ++i) {
                int k = i * 32 + l;
                float sc = s[i] - 0.5f * tns[k];
                if (sc > best) { best = sc; bi = k; }
            }
            #pragma unroll
            for (int m = 1; m < 32; m <<= 1) {
                float so = __shfl_xor_sync(0xffffffffu, best, m, 32);
                int   io = __shfl_xor_sync(0xffffffffu, bi,   m, 32);
                if (so > best || (so == best && io < bi)) { best = so; bi = io; }
            }
            if (l == 0) idxs[r] = bi;
        }
    }
    __syncthreads();

    // ======= epilogue (all-smem, fp16-pair reconstruction ~1ulp): 2 thr/row =======
    float lp = 0.0f;
    {
        const int r = tid >> 1, half = tid & 1;
        const int k = idxs[r];
        const unsigned char* ehp = smem + EH_OFF + k * RS + half * 64;
        const unsigned char* elp = smem + EL_OFF + k * RS + half * 64;
        const unsigned char* xhp = smem + XH_OFF + r * RS + half * 64;
        const unsigned char* xlp = smem + XL_OFF + r * RS + half * 64;
        float4* og = (float4*)(out + (size_t)(row0 + r) * DDIM + half * 32);
        #pragma unroll
        for (int j = 0; j < 8; ++j) {
            uint32_t he  = *(const uint32_t*)(ehp + j * 8);
            uint32_t he2 = *(const uint32_t*)(ehp + j * 8 + 4);
            uint32_t le  = *(const uint32_t*)(elp + j * 8);
            uint32_t le2 = *(const uint32_t*)(elp + j * 8 + 4);
            uint32_t hx  = *(const uint32_t*)(xhp + j * 8);
            uint32_t hx2 = *(const uint32_t*)(xhp + j * 8 + 4);
            uint32_t lx  = *(const uint32_t*)(xlp + j * 8);
            uint32_t lx2 = *(const uint32_t*)(xlp + j * 8 + 4);
            float q0 = hf2f(he, 0) + hf2f(le, 0);
            float q1 = hf2f(he, 1) + hf2f(le, 1);
            float q2 = hf2f(he2, 0) + hf2f(le2, 0);
            float q3 = hf2f(he2, 1) + hf2f(le2, 1);
            float x0 = hf2f(hx, 0) + hf2f(lx, 0);
            float x1 = hf2f(hx, 1) + hf2f(lx, 1);
            float x2 = hf2f(hx2, 0) + hf2f(lx2, 0);
            float x3 = hf2f(hx2, 1) + hf2f(lx2, 1);
            float d0 = q0 - x0, d1 = q1 - x1, d2 = q2 - x2, d3 = q3 - x3;
            lp = fmaf(d0, d0, lp); lp = fmaf(d1, d1, lp);
            lp = fmaf(d2, d2, lp); lp = fmaf(d3, d3, lp);
            og[j] = make_float4(x0 + d0, x1 + d1, x2 + d2, x3 + d3);
        }
    }
    #pragma unroll
    for (int m = 16; m > 0; m >>= 1)
        lp += __shfl_xor_sync(0xffffffffu, lp, m, 32);
    if (l == 0) warpsums[w] = lp;
    __syncthreads();

    // single loss atomic per CTA; last CTA writes the final loss
    if (tid == 0) {
        float s = 0.f;
        #pragma unroll
        for (int i = 0; i < 16; ++i) s += warpsums[i];
        atomicAdd(&g_loss_acc, s);
        __threadfence();
        unsigned int o = atomicAdd(&g_done, 1u);
        if (o == (unsigned)(NBLK - 1)) {
            float tot = atomicAdd(&g_loss_acc, 0.0f);
            out[loss_pos] = 2.0f * tot / 8388608.0f;
        }
    }
}

extern "C" void kernel_launch(void* const* d_in, const int* in_sizes, int n_in,
                              void* d_out, int out_size) {
    const float* x = (const float*)d_in[0];   // [32,4096,64] fp32
    const float* E = (const float*)d_in[1];   // [64,512] fp32
    float* out = (float*)d_out;

    cudaFuncSetAttribute(vq_hmma_kernel,
                         cudaFuncAttributeMaxDynamicSharedMemorySize, SMEM_SZ);

    vq_prep<<<4, 128>>>(E);
    vq_hmma_kernel<<<NBLK, NTHR, SMEM_SZ>>>(x, E, out, out_size - 1);
}